// round 15
// baseline (speedup 1.0000x reference)
#include <cuda_runtime.h>
#include <math.h>
#include <stdint.h>

#define MAXT_C 10000
#define NTH    640
#define ELEMS  16
#define PADT   (NTH * ELEMS)   // 10240
#define NSEG   NTH             // 640 segments of 16
#define MAXB_C 4096
#define TCHUNK 16
#define GRIDY  74              // 2 x 74 = 148 blocks = 1 wave @ 1 block/SM
#define KCAND  3
#define NW     (NTH / 32)      // 20
#define FULLM  0xffffffffu
// Input-independent screen: T2_t <= q0/(1-q0) ~= 1.001e-3; death needs
// u2 > exp(log(1e-12)*T2_0) ~= 0.97271. 0.9720 is safely conservative.
#define U2MIN_GLOB 0.9720f

// Scratch (static __device__ arrays: no allocation allowed)
__device__ float   g_f[PADT];          // exp(acts[t]), zero past T
__device__ float   g_c[PADT];          // LOG_GAMMA + log(1 - f), zero past T
__device__ float4  g_segpart[NSEG];    // per-segment (csum, R, V, 0)
__device__ double  g_prefix[MAXT_C + 1];
__device__ int     g_deathX[MAXB_C];   // atomicMax of (T - death_t); 0 = alive (zero-init OK)
__device__ int     g_elemdone;         // phase-1 counter   (reset by last block)
__device__ int     g_ready;            // phase-1 published (reset by last block)
__device__ int     g_done8[8];         // level-1 arrival   (reset by last block)
__device__ int     g_done;             // level-2 arrival   (reset by last block)

// ---------------------------------------------------------------------------
__device__ __forceinline__ float block_scan_excl_f32(float v, float& total, float* s_warp) {
    int lane = threadIdx.x & 31, w = threadIdx.x >> 5;
    float inc = v;
#pragma unroll
    for (int o = 1; o < 32; o <<= 1) { float n = __shfl_up_sync(FULLM, inc, o); if (lane >= o) inc += n; }
    float exc = __shfl_up_sync(FULLM, inc, 1);
    if (lane == 0) exc = 0.f;
    if (lane == 31) s_warp[w] = inc;
    __syncthreads();
    if (w == 0) {
        float i2 = (lane < NW) ? s_warp[lane] : 0.f;
#pragma unroll
        for (int o = 1; o < 32; o <<= 1) { float n = __shfl_up_sync(FULLM, i2, o); if (lane >= o) i2 += n; }
        float e2 = __shfl_up_sync(FULLM, i2, 1);
        if (lane == 0) e2 = 0.f;
        if (lane < NW) s_warp[lane] = e2;
        if (lane == 31) s_warp[NW] = i2;
    }
    __syncthreads();
    exc += s_warp[w];
    total = s_warp[NW];
    __syncthreads();
    return exc;
}

__device__ __forceinline__ double block_scan_excl_f64(double v, double& total, double* s_warp) {
    int lane = threadIdx.x & 31, w = threadIdx.x >> 5;
    double inc = v;
#pragma unroll
    for (int o = 1; o < 32; o <<= 1) { double n = __shfl_up_sync(FULLM, inc, o); if (lane >= o) inc += n; }
    double exc = __shfl_up_sync(FULLM, inc, 1);
    if (lane == 0) exc = 0.0;
    if (lane == 31) s_warp[w] = inc;
    __syncthreads();
    if (w == 0) {
        double i2 = (lane < NW) ? s_warp[lane] : 0.0;
#pragma unroll
        for (int o = 1; o < 32; o <<= 1) { double n = __shfl_up_sync(FULLM, i2, o); if (lane >= o) i2 += n; }
        double e2 = __shfl_up_sync(FULLM, i2, 1);
        if (lane == 0) e2 = 0.0;
        if (lane < NW) s_warp[lane] = e2;
        if (lane == 31) s_warp[NW] = i2;
    }
    __syncthreads();
    exc += s_warp[w];
    total = s_warp[NW];
    __syncthreads();
    return exc;
}

__device__ __forceinline__ float exp_tiny(float x) {
    if (fabsf(x) < 0.03f)
        return 1.0f + x * (1.0f + x * (0.5f + x * (1.0f / 6.0f)));
    return __expf(x);
}

// ---------------------------------------------------------------------------
// Compute the 16 T2 thresholds of segment `seg` into s_T2f, from smem-resident
// (Wbase, qbase). Warp 0 only; caller must __syncthreads() before use.
__device__ __forceinline__ void compute_T2_smem(int seg, const float* s_W, const float* s_q,
                                                float* s_T2f) {
    if (threadIdx.x < 32) {
        const float ALPHA_F = (float)(log(0.99) / 1000.0);
        int half = threadIdx.x & 15;
        float Wb = s_W[seg], qb = s_q[seg];
        float fe = g_f[seg * 16 + half];
        float ce = g_c[seg * 16 + half];
        float inc = ce;                               // inclusive scan of c, width 16
#pragma unroll
        for (int o = 1; o < 16; o <<= 1) { float n = __shfl_up_sync(FULLM, inc, o, 16); if (half >= o) inc += n; }
        float rt = fe * __expf(inc - ce);             // f_j * e^{localW_j}
        float rinc = rt;
#pragma unroll
        for (int o = 1; o < 16; o <<= 1) { float n = __shfl_up_sync(FULLM, rinc, o, 16); if (half >= o) rinc += n; }
        float rexc = rinc - rt;                       // sum_{k<j} f_k e^{localW_k}
        float q = qb * __expf(ALPHA_F * __expf(Wb) * rexc);
        if (threadIdx.x < 16) s_T2f[half] = q * (1.0f + q + q * q) - 1e-12f;
    }
}

// Cold full resolution of one chunk against s_T2f.
__device__ void cold_resolve(int tstart, int b4, const float* __restrict__ u1,
                             const float* __restrict__ u2, int T, int B,
                             const float* s_T2f) {
    const float4* u2v = (const float4*)u2;
    float4 v[TCHUNK];
#pragma unroll
    for (int t = 0; t < TCHUNK; t++)
        v[t] = (tstart + t < T) ? u2v[((size_t)(tstart + t) * B + b4) >> 2]
                                : make_float4(0.f, 0.f, 0.f, 0.f);
    unsigned m[4] = {0, 0, 0, 0};
#pragma unroll
    for (int t = 0; t < TCHUNK; t++) {
        if (v[t].x > U2MIN_GLOB) m[0] |= 1u << t;
        if (v[t].y > U2MIN_GLOB) m[1] |= 1u << t;
        if (v[t].z > U2MIN_GLOB) m[2] |= 1u << t;
        if (v[t].w > U2MIN_GLOB) m[3] |= 1u << t;
    }
    const float EPSF = 1e-12f;
#pragma unroll
    for (int l = 0; l < 4; l++) {
        unsigned mm = m[l];
        while (mm) {
            int t = __ffs(mm) - 1;
            mm &= mm - 1;
            size_t idx = (size_t)(tstart + t) * B + b4 + l;
            float la = __logf(u2[idx] + EPSF);
            float lb = __logf(u1[idx] + EPSF);
            float rc = (lb < 0.0f) ? __fdividef(la, lb) : 1e30f;
            if (rc < s_T2f[t]) {
                atomicMax(&g_deathX[b4 + l], T - (tstart + t));
                break;
            }
        }
    }
}

// ---------------------------------------------------------------------------
__global__ void __launch_bounds__(NTH, 1)
k_all(const float* __restrict__ acts, const float* __restrict__ u1,
      const float* __restrict__ u2, float* __restrict__ out,
      int T, int B, int nelem, int nblocks) {
    int tid  = threadIdx.x;
    int flat = blockIdx.y * gridDim.x + blockIdx.x;
    int cchunk = (blockIdx.y == 0) ? (GRIDY - 1) : (blockIdx.y - 1);
    int tstart = cchunk * TCHUNK;
    int b4 = (blockIdx.x * NTH + tid) * 4;
    bool lanes_ok = (b4 + 3 < B);
    const float4* u2v = (const float4*)u2;
    const float EPSF = 1e-12f;
    const float LOG_GAMMA_F = (float)log(1.02);
    const float ALPHA_F     = (float)(log(0.99) / 1000.0);
    const float INIT_LOGW_F = (float)log(0.248);
    const float INIT_LOGP_F = (float)log(0.001);

    __shared__ float  s_T2f[TCHUNK];
    __shared__ float  s_warpf[NW + 1];
    __shared__ double s_warpd[NW + 1];
    __shared__ int    s_ired[NW];
    __shared__ float  s_W[NSEG];     // per-segment Wbase (redundant per block)
    __shared__ float  s_q[NSEG];     // per-segment qbase
    __shared__ int    s_tcut;
    __shared__ int    lastFlag;

    // ---- Phase 1: elementwise + per-segment partials (first nelem blocks) ----
    if (flat < nelem) {
        int i = flat * NTH + tid;
        int half = tid & 15;
        float fv = 0.f, cv = 0.f;
        if (i < T) { fv = __expf(acts[i]); cv = LOG_GAMMA_F + __logf(1.f - fv); }
        if (i < PADT) { g_f[i] = fv; g_c[i] = cv; }
        float inc = cv;                               // inclusive scan of c, width 16
#pragma unroll
        for (int o = 1; o < 16; o <<= 1) { float n = __shfl_up_sync(FULLM, inc, o, 16); if (half >= o) inc += n; }
        float rt = (i < T) ? fv * __expf(inc - cv) : 0.f;   // f_j e^{localW_j}
        float vt = (i < T) ? __expf(inc * 0.001f) : 0.f;    // e^{localW_{j+1}/1000}
        float rs = rt, vs = vt;
#pragma unroll
        for (int o = 8; o > 0; o >>= 1) {
            rs += __shfl_xor_sync(FULLM, rs, o, 16);
            vs += __shfl_xor_sync(FULLM, vs, o, 16);
        }
        float cs = __shfl_sync(FULLM, inc, 15, 16);
        if (half == 0 && i < PADT) g_segpart[i >> 4] = make_float4(cs, rs, vs, 0.f);
        __syncthreads();
        if (tid == 0) {
            __threadfence();
            if (atomicAdd(&g_elemdone, 1) == nelem - 1) g_ready = 1;  // single publish
        }
    }

    // ---- Pre-ready (overlapped): u2 screen + candidate rc for own chunk ----
    int cnt[4] = {0, 0, 0, 0};
    int ct[4][KCAND];
    float cu[4][KCAND];
    if (lanes_ok) {
        float4 v[TCHUNK];
#pragma unroll
        for (int t = 0; t < TCHUNK; t++)
            v[t] = (tstart + t < T) ? u2v[((size_t)(tstart + t) * B + b4) >> 2]
                                    : make_float4(0.f, 0.f, 0.f, 0.f);
#pragma unroll
        for (int t = 0; t < TCHUNK; t++) {
#pragma unroll
            for (int l = 0; l < 4; l++) {
                float uv = (l == 0) ? v[t].x : (l == 1) ? v[t].y : (l == 2) ? v[t].z : v[t].w;
                if (uv > U2MIN_GLOB) {
                    int n = cnt[l];
                    if (n == 0)      { ct[l][0] = t; cu[l][0] = uv; }
                    else if (n == 1) { ct[l][1] = t; cu[l][1] = uv; }
                    else if (n == 2) { ct[l][2] = t; cu[l][2] = uv; }
                    cnt[l] = n + 1;
                }
            }
        }
    }
    float crc[4][KCAND];
#pragma unroll
    for (int l = 0; l < 4; l++) {
#pragma unroll
        for (int k = 0; k < KCAND; k++) {
            if (cnt[l] > k) {
                size_t idx = (size_t)(tstart + ct[l][k]) * B + b4 + l;
                float la = __logf(cu[l][k] + EPSF);
                float lb = __logf(u1[idx] + EPSF);
                crc[l][k] = (lb < 0.0f) ? __fdividef(la, lb) : 1e30f;
            }
        }
    }

    // ---- Ready wait (plain volatile loads: no atomic serialization) ----
    if (tid == 0) {
        volatile int* vr = &g_ready;
        while (*vr == 0) __nanosleep(64);
    }
    __syncthreads();
    __threadfence();

    // ---- Redundant base scan (EVERY block; removes the flag handoff) ----
    float4 sp = g_segpart[tid];
    float ctot;
    float Wbase = block_scan_excl_f32(sp.x, ctot, s_warpf) + INIT_LOGW_F;
    float dfs = ALPHA_F * sp.y * __expf(Wbase);
    float dtot;
    float Pbase = block_scan_excl_f32(dfs, dtot, s_warpf) + INIT_LOGP_F;
    float qbase = __expf(Pbase);
    s_W[tid] = Wbase;
    s_q[tid] = qbase;
    // tcut = 16 * (1 + highest segment with qbase >= 1.4e-11)
    {
        unsigned bal = __ballot_sync(FULLM, qbase >= 1.4e-11f);
        int lane = tid & 31, w = tid >> 5;
        int wmax = bal ? (w * 32 + (31 - __clz(bal)) + 1) : 0;
        if (lane == 0) s_ired[w] = wmax;
    }
    __syncthreads();
    if (tid < 32) {
        int vv = (tid < NW) ? s_ired[tid] : 0;
#pragma unroll
        for (int o = 16; o > 0; o >>= 1) vv = max(vv, __shfl_down_sync(FULLM, vv, o));
        if (tid == 0) s_tcut = vv * TCHUNK;
    }
    __syncthreads();
    int tcut = s_tcut;

    // ---- Own-chunk resolution: T2 + precomputed-rc compares ----
    bool active = (tstart < tcut);
    if (active) compute_T2_smem(cchunk, s_W, s_q, s_T2f);
    __syncthreads();
    if (active && lanes_ok) {
#pragma unroll
        for (int l = 0; l < 4; l++) {
            int death_t = -1;
#pragma unroll
            for (int k = 0; k < KCAND; k++) {
                if (death_t < 0 && cnt[l] > k && crc[l][k] < s_T2f[ct[l][k]])
                    death_t = ct[l][k];
            }
            if (death_t < 0 && cnt[l] > KCAND) {
                for (int t = ct[l][KCAND - 1] + 1; t < TCHUNK; t++) {
                    size_t idx = (size_t)(tstart + t) * B + b4 + l;
                    float uv = u2[idx];
                    if (uv > U2MIN_GLOB) {
                        float la = __logf(uv + EPSF);
                        float lb = __logf(u1[idx] + EPSF);
                        float rc = (lb < 0.0f) ? __fdividef(la, lb) : 1e30f;
                        if (rc < s_T2f[t]) { death_t = t; break; }
                    }
                }
            }
            if (death_t >= 0)
                atomicMax(&g_deathX[b4 + l], T - (tstart + death_t));
        }
    }

    // ---- Block 0 only: fp64 S scan + prefix writes (overlaps others' arrival) ----
    if (flat == 0) {
        float wvs = sp.z * __expf(Wbase * 0.001f);
        double tot;
        double Sbase = block_scan_excl_f64((double)wvs, tot, s_warpd);
        const float4* c4 = (const float4*)g_c;
        float v = __expf(Wbase * 0.001f);
        float ls = 0.f;
#pragma unroll
        for (int k = 0; k < 4; k++) {
            float4 c = c4[tid * 4 + k];
#pragma unroll
            for (int u = 0; u < 4; u++) {
                float ce = (u == 0) ? c.x : (u == 1) ? c.y : (u == 2) ? c.z : c.w;
                int i = tid * 16 + k * 4 + u;
                v *= exp_tiny(ce * 0.001f);
                if (i < T) { g_prefix[i] = Sbase + (double)ls; ls += v; }
            }
        }
        if (tid == 0) g_prefix[T] = tot;
    }

    // ---- Generic tail (never runs for this shape: tcut <= GRIDY*TCHUNK) ----
    for (int chunk = cchunk + GRIDY; chunk * TCHUNK < tcut; chunk += GRIDY) {
        __syncthreads();
        compute_T2_smem(chunk, s_W, s_q, s_T2f);
        __syncthreads();
        if (lanes_ok) cold_resolve(chunk * TCHUNK, b4, u1, u2, T, B, s_T2f);
    }

    // ---- Completion: two-level arrival; final arriver reduces + resets ----
    if (tid == 0) {
        __threadfence();
        int bucket = flat & 7;
        int quota = (nblocks - bucket + 7) >> 3;
        int lf = 0;
        if (atomicAdd(&g_done8[bucket], 1) == quota - 1)
            lf = (atomicAdd(&g_done, 1) == 7);
        lastFlag = lf;
    }
    __syncthreads();
    if (!lastFlag) return;

    __shared__ double s_red[NW];
    double s = 0.0;
    for (int i = tid; i < B; i += NTH)
        s += g_prefix[T - g_deathX[i]];              // deathX=0 (alive) -> prefix[T]
#pragma unroll
    for (int o = 16; o > 0; o >>= 1) s += __shfl_down_sync(FULLM, s, o);
    if ((tid & 31) == 0) s_red[tid >> 5] = s;
    __syncthreads();
    if (tid < 32) {
        double v = (tid < NW) ? s_red[tid] : 0.0;
#pragma unroll
        for (int o = 16; o > 0; o >>= 1) v += __shfl_down_sync(FULLM, v, o);
        if (tid == 0) out[0] = (float)(v / (double)B);
    }
    __syncthreads();
    for (int i = tid; i < B; i += NTH) g_deathX[i] = 0;   // reset for next replay
    if (tid < 8) g_done8[tid] = 0;
    if (tid == 0) { g_ready = 0; g_elemdone = 0; g_done = 0; }
}

extern "C" void kernel_launch(void* const* d_in, const int* in_sizes, int n_in,
                              void* d_out, int out_size) {
    const float* acts = (const float*)d_in[0];
    const float* u1   = (const float*)d_in[1];
    const float* u2   = (const float*)d_in[2];
    int T = in_sizes[0];
    int B = (T > 0) ? (in_sizes[1] / T) : 0;

    int gx = (B + NTH * 4 - 1) / (NTH * 4);           // 2 for B=4096
    dim3 grid(gx, GRIDY);                             // 148 blocks total
    int nblocks = gx * GRIDY;
    int nelem = PADT / NTH;                           // 16
    k_all<<<grid, NTH>>>(acts, u1, u2, (float*)d_out, T, B, nelem, nblocks);
}

// round 16
// speedup vs baseline: 1.0564x; 1.0564x over previous
#include <cuda_runtime.h>
#include <math.h>
#include <stdint.h>

#define MAXT_C 10000
#define NTH    640
#define ELEMS  16
#define PADT   (NTH * ELEMS)   // 10240
#define NSEG   NTH             // 640 segments of 16
#define MAXB_C 4096
#define TCHUNK 16
#define GRIDY  74              // 2 x 74 = 148 blocks = 1 wave @ 1 block/SM
#define KCAND  3
#define NW     (NTH / 32)      // 20
#define FULLM  0xffffffffu
// Input-independent screen: T2_t <= q0/(1-q0) ~= 1.001e-3; death needs
// u2 > exp(log(1e-12)*T2_0) ~= 0.97271. 0.9720 is safely conservative.
#define U2MIN_GLOB 0.9720f

// Scratch (static __device__ arrays: no allocation allowed)
__device__ float   g_f[PADT];          // exp(acts[t]), zero past T
__device__ float   g_c[PADT];          // LOG_GAMMA + log(1 - f), zero past T
__device__ float4  g_segpart[NSEG];    // per-segment (csum, R, V, 0)
__device__ float2  g_wq[NSEG];         // per-segment (Wbase, qbase)
__device__ double  g_prefix[MAXT_C + 1];
__device__ int     g_deathX[MAXB_C];   // atomicMax of (T - death_t); 0 = alive (zero-init OK)
__device__ int     g_elemdone;         // phase-1 counter        (reset by last block)
__device__ int     g_ready;            // phase-1 single publish (reset by last block)
__device__ int     g_flag;             // tcut+1 when published  (reset by last block)
__device__ int     g_done8[8];         // level-1 arrival        (reset by last block)
__device__ int     g_done;             // level-2 arrival        (reset by last block)

// ---------------------------------------------------------------------------
__device__ __forceinline__ float block_scan_excl_f32(float v, float& total, float* s_warp) {
    int lane = threadIdx.x & 31, w = threadIdx.x >> 5;
    float inc = v;
#pragma unroll
    for (int o = 1; o < 32; o <<= 1) { float n = __shfl_up_sync(FULLM, inc, o); if (lane >= o) inc += n; }
    float exc = __shfl_up_sync(FULLM, inc, 1);
    if (lane == 0) exc = 0.f;
    if (lane == 31) s_warp[w] = inc;
    __syncthreads();
    if (w == 0) {
        float i2 = (lane < NW) ? s_warp[lane] : 0.f;
#pragma unroll
        for (int o = 1; o < 32; o <<= 1) { float n = __shfl_up_sync(FULLM, i2, o); if (lane >= o) i2 += n; }
        float e2 = __shfl_up_sync(FULLM, i2, 1);
        if (lane == 0) e2 = 0.f;
        if (lane < NW) s_warp[lane] = e2;
        if (lane == 31) s_warp[NW] = i2;
    }
    __syncthreads();
    exc += s_warp[w];
    total = s_warp[NW];
    __syncthreads();
    return exc;
}

__device__ __forceinline__ double block_scan_excl_f64(double v, double& total, double* s_warp) {
    int lane = threadIdx.x & 31, w = threadIdx.x >> 5;
    double inc = v;
#pragma unroll
    for (int o = 1; o < 32; o <<= 1) { double n = __shfl_up_sync(FULLM, inc, o); if (lane >= o) inc += n; }
    double exc = __shfl_up_sync(FULLM, inc, 1);
    if (lane == 0) exc = 0.0;
    if (lane == 31) s_warp[w] = inc;
    __syncthreads();
    if (w == 0) {
        double i2 = (lane < NW) ? s_warp[lane] : 0.0;
#pragma unroll
        for (int o = 1; o < 32; o <<= 1) { double n = __shfl_up_sync(FULLM, i2, o); if (lane >= o) i2 += n; }
        double e2 = __shfl_up_sync(FULLM, i2, 1);
        if (lane == 0) e2 = 0.0;
        if (lane < NW) s_warp[lane] = e2;
        if (lane == 31) s_warp[NW] = i2;
    }
    __syncthreads();
    exc += s_warp[w];
    total = s_warp[NW];
    __syncthreads();
    return exc;
}

__device__ __forceinline__ float exp_tiny(float x) {
    if (fabsf(x) < 0.03f)
        return 1.0f + x * (1.0f + x * (0.5f + x * (1.0f / 6.0f)));
    return __expf(x);
}

// ---------------------------------------------------------------------------
// Cold-path T2 (reads g_f/g_c + g_wq). Warp 0 only; sync before using s_T2f.
__device__ __forceinline__ void compute_T2_smem(int seg, float* s_T2f) {
    if (threadIdx.x < 32) {
        const float ALPHA_F = (float)(log(0.99) / 1000.0);
        int half = threadIdx.x & 15;
        float2 wq = g_wq[seg];
        float fe = g_f[seg * 16 + half];
        float ce = g_c[seg * 16 + half];
        float inc = ce;
#pragma unroll
        for (int o = 1; o < 16; o <<= 1) { float n = __shfl_up_sync(FULLM, inc, o, 16); if (half >= o) inc += n; }
        float rt = fe * __expf(inc - ce);
        float rinc = rt;
#pragma unroll
        for (int o = 1; o < 16; o <<= 1) { float n = __shfl_up_sync(FULLM, rinc, o, 16); if (half >= o) rinc += n; }
        float rexc = rinc - rt;
        float q = wq.y * __expf(ALPHA_F * __expf(wq.x) * rexc);
        if (threadIdx.x < 16) s_T2f[half] = q * (1.0f + q + q * q) - 1e-12f;
    }
}

// Cold full resolution of one chunk against s_T2f.
__device__ void cold_resolve(int tstart, int b4, const float* __restrict__ u1,
                             const float* __restrict__ u2, int T, int B,
                             const float* s_T2f) {
    const float4* u2v = (const float4*)u2;
    float4 v[TCHUNK];
#pragma unroll
    for (int t = 0; t < TCHUNK; t++)
        v[t] = (tstart + t < T) ? u2v[((size_t)(tstart + t) * B + b4) >> 2]
                                : make_float4(0.f, 0.f, 0.f, 0.f);
    unsigned m[4] = {0, 0, 0, 0};
#pragma unroll
    for (int t = 0; t < TCHUNK; t++) {
        if (v[t].x > U2MIN_GLOB) m[0] |= 1u << t;
        if (v[t].y > U2MIN_GLOB) m[1] |= 1u << t;
        if (v[t].z > U2MIN_GLOB) m[2] |= 1u << t;
        if (v[t].w > U2MIN_GLOB) m[3] |= 1u << t;
    }
    const float EPSF = 1e-12f;
#pragma unroll
    for (int l = 0; l < 4; l++) {
        unsigned mm = m[l];
        while (mm) {
            int t = __ffs(mm) - 1;
            mm &= mm - 1;
            size_t idx = (size_t)(tstart + t) * B + b4 + l;
            float la = __logf(u2[idx] + EPSF);
            float lb = __logf(u1[idx] + EPSF);
            float rc = (lb < 0.0f) ? __fdividef(la, lb) : 1e30f;
            if (rc < s_T2f[t]) {
                atomicMax(&g_deathX[b4 + l], T - (tstart + t));
                break;
            }
        }
    }
}

// ---------------------------------------------------------------------------
__global__ void __launch_bounds__(NTH, 1)
k_all(const float* __restrict__ acts, const float* __restrict__ u1,
      const float* __restrict__ u2, float* __restrict__ out,
      int T, int B, int nelem, int nblocks) {
    int tid  = threadIdx.x;
    int flat = blockIdx.y * gridDim.x + blockIdx.x;
    bool producer = (flat == 0);
    int cchunk = (blockIdx.y == 0) ? (GRIDY - 1) : (blockIdx.y - 1);
    int tstart = cchunk * TCHUNK;
    int b4 = (blockIdx.x * NTH + tid) * 4;
    bool lanes_ok = (b4 + 3 < B);
    const float4* u2v = (const float4*)u2;
    const float EPSF = 1e-12f;
    const float LOG_GAMMA_F = (float)log(1.02);
    const float ALPHA_F     = (float)(log(0.99) / 1000.0);
    const float INIT_LOGW_F = (float)log(0.248);
    const float INIT_LOGP_F = (float)log(0.001);

    __shared__ float  s_T2f[TCHUNK];
    __shared__ float  s_warpf[NW + 1];
    __shared__ double s_warpd[NW + 1];
    __shared__ int    s_ired[NW];
    __shared__ int    s_tcut;
    __shared__ int    lastFlag;

    // ---- Phase 1: elementwise + per-segment partials (first nelem blocks) ----
    if (flat < nelem) {
        int i = flat * NTH + tid;
        int half = tid & 15;
        float fv = 0.f, cv = 0.f;
        if (i < T) { fv = __expf(acts[i]); cv = LOG_GAMMA_F + __logf(1.f - fv); }
        if (i < PADT) { g_f[i] = fv; g_c[i] = cv; }
        float inc = cv;                               // inclusive scan of c, width 16
#pragma unroll
        for (int o = 1; o < 16; o <<= 1) { float n = __shfl_up_sync(FULLM, inc, o, 16); if (half >= o) inc += n; }
        float rt = (i < T) ? fv * __expf(inc - cv) : 0.f;   // f_j e^{localW_j}
        float vt = (i < T) ? __expf(inc * 0.001f) : 0.f;    // e^{localW_{j+1}/1000}
        float rs = rt, vs = vt;
#pragma unroll
        for (int o = 8; o > 0; o >>= 1) {
            rs += __shfl_xor_sync(FULLM, rs, o, 16);
            vs += __shfl_xor_sync(FULLM, vs, o, 16);
        }
        float cs = __shfl_sync(FULLM, inc, 15, 16);
        if (half == 0 && i < PADT) g_segpart[i >> 4] = make_float4(cs, rs, vs, 0.f);
        __syncthreads();
        if (tid == 0) {
            __threadfence();
            if (atomicAdd(&g_elemdone, 1) == nelem - 1) g_ready = 1;  // single publish
        }
    }

    if (producer) {
        // ---- Producer: minimal pre-flag path (volatile ready wait) ----
        if (tid == 0) {
            volatile int* vr = &g_ready;
            while (*vr == 0) __nanosleep(64);
        }
        __syncthreads();
        __threadfence();
        float4 sp = g_segpart[tid];
        float ctot;
        float Wbase = block_scan_excl_f32(sp.x, ctot, s_warpf) + INIT_LOGW_F;
        float dfs = ALPHA_F * sp.y * __expf(Wbase);
        float dtot;
        float Pbase = block_scan_excl_f32(dfs, dtot, s_warpf) + INIT_LOGP_F;
        float qbase = __expf(Pbase);
        g_wq[tid] = make_float2(Wbase, qbase);
        // tcut = 16 * (1 + highest segment with qbase >= 1.4e-11)
        unsigned bal = __ballot_sync(FULLM, qbase >= 1.4e-11f);
        int lane = tid & 31, w = tid >> 5;
        int wmax = bal ? (w * 32 + (31 - __clz(bal)) + 1) : 0;
        if (lane == 0) s_ired[w] = wmax;
        __syncthreads();
        if (tid < 32) {
            int vv = (tid < NW) ? s_ired[tid] : 0;
#pragma unroll
            for (int o = 16; o > 0; o >>= 1) vv = max(vv, __shfl_down_sync(FULLM, vv, o));
            if (tid == 0) {
                s_tcut = vv * TCHUNK;
                __threadfence();
                atomicExch(&g_flag, vv * TCHUNK + 1);   // publish EARLY
            }
        }
        __syncthreads();
        // ---- Post-flag (overlaps consumers): S scan + prefix writes ----
        float wvs = sp.z * __expf(Wbase * 0.001f);
        double tot;
        double Sbase = block_scan_excl_f64((double)wvs, tot, s_warpd);
        {
            const float4* c4 = (const float4*)g_c;
            float v = __expf(Wbase * 0.001f);
            float ls = 0.f;
#pragma unroll
            for (int k = 0; k < 4; k++) {
                float4 c = c4[tid * 4 + k];
#pragma unroll
                for (int u = 0; u < 4; u++) {
                    float ce = (u == 0) ? c.x : (u == 1) ? c.y : (u == 2) ? c.z : c.w;
                    int i = tid * 16 + k * 4 + u;
                    v *= exp_tiny(ce * 0.001f);
                    if (i < T) { g_prefix[i] = Sbase + (double)ls; ls += v; }
                }
            }
        }
        if (tid == 0) g_prefix[T] = tot;
        // generic tail (never runs for this shape)
        int tcut = s_tcut;
        for (int chunk = cchunk; chunk * TCHUNK < tcut; chunk += GRIDY) {
            __syncthreads();
            compute_T2_smem(chunk, s_T2f);
            __syncthreads();
            if (lanes_ok) cold_resolve(chunk * TCHUNK, b4, u1, u2, T, B, s_T2f);
        }
    } else {
        // ---- Consumer pre-flag (overlapped): screen + candidate rc ----
        int cnt[4] = {0, 0, 0, 0};
        int ct[4][KCAND];
        float cu[4][KCAND];
        if (lanes_ok) {
            float4 v[TCHUNK];
#pragma unroll
            for (int t = 0; t < TCHUNK; t++)
                v[t] = (tstart + t < T) ? u2v[((size_t)(tstart + t) * B + b4) >> 2]
                                        : make_float4(0.f, 0.f, 0.f, 0.f);
#pragma unroll
            for (int t = 0; t < TCHUNK; t++) {
#pragma unroll
                for (int l = 0; l < 4; l++) {
                    float uv = (l == 0) ? v[t].x : (l == 1) ? v[t].y : (l == 2) ? v[t].z : v[t].w;
                    if (uv > U2MIN_GLOB) {
                        int n = cnt[l];
                        if (n == 0)      { ct[l][0] = t; cu[l][0] = uv; }
                        else if (n == 1) { ct[l][1] = t; cu[l][1] = uv; }
                        else if (n == 2) { ct[l][2] = t; cu[l][2] = uv; }
                        cnt[l] = n + 1;
                    }
                }
            }
        }
        float crc[4][KCAND];
#pragma unroll
        for (int l = 0; l < 4; l++) {
#pragma unroll
            for (int k = 0; k < KCAND; k++) {
                if (cnt[l] > k) {
                    size_t idx = (size_t)(tstart + ct[l][k]) * B + b4 + l;
                    float la = __logf(cu[l][k] + EPSF);
                    float lb = __logf(u1[idx] + EPSF);
                    crc[l][k] = (lb < 0.0f) ? __fdividef(la, lb) : 1e30f;
                }
            }
        }
        // ---- NEW pre-flag: warp 0 derives its chunk's scan intermediates
        //      directly from acts (no post-flag g_f/g_c loads) ----
        float rexc = 0.f;
        if (tid < 32) {
            int half = tid & 15;
            int i = tstart + half;
            float fe = 0.f, ce = 0.f;
            if (i < T) { fe = __expf(acts[i]); ce = LOG_GAMMA_F + __logf(1.f - fe); }
            float inc = ce;
#pragma unroll
            for (int o = 1; o < 16; o <<= 1) { float n = __shfl_up_sync(FULLM, inc, o, 16); if (half >= o) inc += n; }
            float rt = (i < T) ? fe * __expf(inc - ce) : 0.f;
            float rinc = rt;
#pragma unroll
            for (int o = 1; o < 16; o <<= 1) { float n = __shfl_up_sync(FULLM, rinc, o, 16); if (half >= o) rinc += n; }
            rexc = rinc - rt;
        }
        // ---- Flag wait (value = tcut + 1) ----
        if (tid == 0) {
            volatile int* vf = &g_flag;
            int fv;
            while ((fv = *vf) == 0) __nanosleep(64);
            s_tcut = fv - 1;
        }
        __syncthreads();
        __threadfence();
        int tcut = s_tcut;
        bool active = (tstart < tcut);
        // ---- Post-flag: ONE float2 load + 3 MUFU + compares ----
        if (active && tid < 32) {
            float2 wq = g_wq[cchunk];
            float q = wq.y * __expf(ALPHA_F * __expf(wq.x) * rexc);
            if (tid < 16) s_T2f[tid] = q * (1.0f + q + q * q) - 1e-12f;
        }
        __syncthreads();
        if (active && lanes_ok) {
#pragma unroll
            for (int l = 0; l < 4; l++) {
                int death_t = -1;
#pragma unroll
                for (int k = 0; k < KCAND; k++) {
                    if (death_t < 0 && cnt[l] > k && crc[l][k] < s_T2f[ct[l][k]])
                        death_t = ct[l][k];
                }
                if (death_t < 0 && cnt[l] > KCAND) {
                    for (int t = ct[l][KCAND - 1] + 1; t < TCHUNK; t++) {
                        size_t idx = (size_t)(tstart + t) * B + b4 + l;
                        float uv = u2[idx];
                        if (uv > U2MIN_GLOB) {
                            float la = __logf(uv + EPSF);
                            float lb = __logf(u1[idx] + EPSF);
                            float rc = (lb < 0.0f) ? __fdividef(la, lb) : 1e30f;
                            if (rc < s_T2f[t]) { death_t = t; break; }
                        }
                    }
                }
                if (death_t >= 0)
                    atomicMax(&g_deathX[b4 + l], T - (tstart + death_t));
            }
        }
        // generic tail (never runs for this shape)
        for (int chunk = cchunk + GRIDY; chunk * TCHUNK < tcut; chunk += GRIDY) {
            __syncthreads();
            compute_T2_smem(chunk, s_T2f);
            __syncthreads();
            if (lanes_ok) cold_resolve(chunk * TCHUNK, b4, u1, u2, T, B, s_T2f);
        }
    }

    // ---- Completion: two-level arrival; final arriver reduces + resets ----
    if (tid == 0) {
        __threadfence();
        int bucket = flat & 7;
        int quota = (nblocks - bucket + 7) >> 3;
        int lf = 0;
        if (atomicAdd(&g_done8[bucket], 1) == quota - 1)
            lf = (atomicAdd(&g_done, 1) == 7);
        lastFlag = lf;
    }
    __syncthreads();
    if (!lastFlag) return;

    __shared__ double s_red[NW];
    double s = 0.0;
    for (int i = tid; i < B; i += NTH)
        s += g_prefix[T - g_deathX[i]];              // deathX=0 (alive) -> prefix[T]
#pragma unroll
    for (int o = 16; o > 0; o >>= 1) s += __shfl_down_sync(FULLM, s, o);
    if ((tid & 31) == 0) s_red[tid >> 5] = s;
    __syncthreads();
    if (tid < 32) {
        double v = (tid < NW) ? s_red[tid] : 0.0;
#pragma unroll
        for (int o = 16; o > 0; o >>= 1) v += __shfl_down_sync(FULLM, v, o);
        if (tid == 0) out[0] = (float)(v / (double)B);
    }
    __syncthreads();
    for (int i = tid; i < B; i += NTH) g_deathX[i] = 0;   // reset for next replay
    if (tid < 8) g_done8[tid] = 0;
    if (tid == 0) { g_ready = 0; g_flag = 0; g_elemdone = 0; g_done = 0; }
}

extern "C" void kernel_launch(void* const* d_in, const int* in_sizes, int n_in,
                              void* d_out, int out_size) {
    const float* acts = (const float*)d_in[0];
    const float* u1   = (const float*)d_in[1];
    const float* u2   = (const float*)d_in[2];
    int T = in_sizes[0];
    int B = (T > 0) ? (in_sizes[1] / T) : 0;

    int gx = (B + NTH * 4 - 1) / (NTH * 4);           // 2 for B=4096
    dim3 grid(gx, GRIDY);                             // 148 blocks total
    int nblocks = gx * GRIDY;
    int nelem = PADT / NTH;                           // 16
    k_all<<<grid, NTH>>>(acts, u1, u2, (float*)d_out, T, B, nelem, nblocks);
}

// round 17
// speedup vs baseline: 1.0920x; 1.0337x over previous
#include <cuda_runtime.h>
#include <math.h>
#include <stdint.h>

#define MAXT_C 10000
#define NTH    640
#define ELEMS  16
#define PADT   (NTH * ELEMS)   // 10240
#define NSEG   NTH             // 640 segments of 16
#define MAXB_C 4096
#define TCHUNK 16
#define GRIDY  74              // 2 x 74 = 148 blocks = 1 wave @ 1 block/SM
#define KCAND  3
#define NW     (NTH / 32)      // 20
#define FULLM  0xffffffffu
// Input-independent screen: T2_t <= q0/(1-q0) ~= 1.001e-3; death needs
// u2 > exp(log(1e-12)*T2_0) ~= 0.97271. 0.9720 is safely conservative.
#define U2MIN_GLOB 0.9720f

// Scratch (static __device__ arrays: no allocation allowed)
__device__ float   g_f[PADT];          // exp(acts[t]), zero past T
__device__ float   g_c[PADT];          // LOG_GAMMA + log(1 - f), zero past T
__device__ float4  g_segpart[NSEG];    // per-segment (csum, R, V, 0)
__device__ float2  g_wq[NSEG];         // per-segment (Wbase, qbase); zero = not ready
__device__ double  g_prefix[MAXT_C + 1];
__device__ int     g_deathX[MAXB_C];   // atomicMax of (T - death_t); 0 = alive (zero-init OK)
__device__ int     g_elemdone;         // phase-1 counter        (reset by last block)
__device__ int     g_flag;             // tcut+1 when published  (reset by last block)
__device__ int     g_done8[8];         // level-1 arrival        (reset by last block)
__device__ int     g_done;             // level-2 arrival        (reset by last block)

// ---------------------------------------------------------------------------
__device__ __forceinline__ float block_scan_excl_f32(float v, float& total, float* s_warp) {
    int lane = threadIdx.x & 31, w = threadIdx.x >> 5;
    float inc = v;
#pragma unroll
    for (int o = 1; o < 32; o <<= 1) { float n = __shfl_up_sync(FULLM, inc, o); if (lane >= o) inc += n; }
    float exc = __shfl_up_sync(FULLM, inc, 1);
    if (lane == 0) exc = 0.f;
    if (lane == 31) s_warp[w] = inc;
    __syncthreads();
    if (w == 0) {
        float i2 = (lane < NW) ? s_warp[lane] : 0.f;
#pragma unroll
        for (int o = 1; o < 32; o <<= 1) { float n = __shfl_up_sync(FULLM, i2, o); if (lane >= o) i2 += n; }
        float e2 = __shfl_up_sync(FULLM, i2, 1);
        if (lane == 0) e2 = 0.f;
        if (lane < NW) s_warp[lane] = e2;
        if (lane == 31) s_warp[NW] = i2;
    }
    __syncthreads();
    exc += s_warp[w];
    total = s_warp[NW];
    __syncthreads();
    return exc;
}

__device__ __forceinline__ double block_scan_excl_f64(double v, double& total, double* s_warp) {
    int lane = threadIdx.x & 31, w = threadIdx.x >> 5;
    double inc = v;
#pragma unroll
    for (int o = 1; o < 32; o <<= 1) { double n = __shfl_up_sync(FULLM, inc, o); if (lane >= o) inc += n; }
    double exc = __shfl_up_sync(FULLM, inc, 1);
    if (lane == 0) exc = 0.0;
    if (lane == 31) s_warp[w] = inc;
    __syncthreads();
    if (w == 0) {
        double i2 = (lane < NW) ? s_warp[lane] : 0.0;
#pragma unroll
        for (int o = 1; o < 32; o <<= 1) { double n = __shfl_up_sync(FULLM, i2, o); if (lane >= o) i2 += n; }
        double e2 = __shfl_up_sync(FULLM, i2, 1);
        if (lane == 0) e2 = 0.0;
        if (lane < NW) s_warp[lane] = e2;
        if (lane == 31) s_warp[NW] = i2;
    }
    __syncthreads();
    exc += s_warp[w];
    total = s_warp[NW];
    __syncthreads();
    return exc;
}

__device__ __forceinline__ float exp_tiny(float x) {
    if (fabsf(x) < 0.03f)
        return 1.0f + x * (1.0f + x * (0.5f + x * (1.0f / 6.0f)));
    return __expf(x);
}

// ---------------------------------------------------------------------------
// Cold-path T2 (reads g_f/g_c + g_wq). Warp 0 only; sync before using s_T2f.
__device__ __forceinline__ void compute_T2_smem(int seg, float* s_T2f) {
    if (threadIdx.x < 32) {
        const float ALPHA_F = (float)(log(0.99) / 1000.0);
        int half = threadIdx.x & 15;
        float2 wq = g_wq[seg];
        float fe = g_f[seg * 16 + half];
        float ce = g_c[seg * 16 + half];
        float inc = ce;
#pragma unroll
        for (int o = 1; o < 16; o <<= 1) { float n = __shfl_up_sync(FULLM, inc, o, 16); if (half >= o) inc += n; }
        float rt = fe * __expf(inc - ce);
        float rinc = rt;
#pragma unroll
        for (int o = 1; o < 16; o <<= 1) { float n = __shfl_up_sync(FULLM, rinc, o, 16); if (half >= o) rinc += n; }
        float rexc = rinc - rt;
        float q = wq.y * __expf(ALPHA_F * __expf(wq.x) * rexc);
        if (threadIdx.x < 16) s_T2f[half] = q * (1.0f + q + q * q) - 1e-12f;
    }
}

// Cold full resolution of one chunk against s_T2f.
__device__ void cold_resolve(int tstart, int b4, const float* __restrict__ u1,
                             const float* __restrict__ u2, int T, int B,
                             const float* s_T2f) {
    const float4* u2v = (const float4*)u2;
    float4 v[TCHUNK];
#pragma unroll
    for (int t = 0; t < TCHUNK; t++)
        v[t] = (tstart + t < T) ? u2v[((size_t)(tstart + t) * B + b4) >> 2]
                                : make_float4(0.f, 0.f, 0.f, 0.f);
    unsigned m[4] = {0, 0, 0, 0};
#pragma unroll
    for (int t = 0; t < TCHUNK; t++) {
        if (v[t].x > U2MIN_GLOB) m[0] |= 1u << t;
        if (v[t].y > U2MIN_GLOB) m[1] |= 1u << t;
        if (v[t].z > U2MIN_GLOB) m[2] |= 1u << t;
        if (v[t].w > U2MIN_GLOB) m[3] |= 1u << t;
    }
    const float EPSF = 1e-12f;
#pragma unroll
    for (int l = 0; l < 4; l++) {
        unsigned mm = m[l];
        while (mm) {
            int t = __ffs(mm) - 1;
            mm &= mm - 1;
            size_t idx = (size_t)(tstart + t) * B + b4 + l;
            float la = __logf(u2[idx] + EPSF);
            float lb = __logf(u1[idx] + EPSF);
            float rc = (lb < 0.0f) ? __fdividef(la, lb) : 1e30f;
            if (rc < s_T2f[t]) {
                atomicMax(&g_deathX[b4 + l], T - (tstart + t));
                break;
            }
        }
    }
}

// ---------------------------------------------------------------------------
__global__ void __launch_bounds__(NTH, 1)
k_all(const float* __restrict__ acts, const float* __restrict__ u1,
      const float* __restrict__ u2, float* __restrict__ out,
      int T, int B, int nelem, int nblocks) {
    int tid  = threadIdx.x;
    int flat = blockIdx.y * gridDim.x + blockIdx.x;
    bool producer = (flat == 0);
    int cchunk = (blockIdx.y == 0) ? (GRIDY - 1) : (blockIdx.y - 1);
    int tstart = cchunk * TCHUNK;
    int b4 = (blockIdx.x * NTH + tid) * 4;
    bool lanes_ok = (b4 + 3 < B);
    const float4* u2v = (const float4*)u2;
    const float EPSF = 1e-12f;
    const float LOG_GAMMA_F = (float)log(1.02);
    const float ALPHA_F     = (float)(log(0.99) / 1000.0);
    const float INIT_LOGW_F = (float)log(0.248);
    const float INIT_LOGP_F = (float)log(0.001);

    __shared__ float  s_T2f[TCHUNK];
    __shared__ float  s_warpf[NW + 1];
    __shared__ double s_warpd[NW + 1];
    __shared__ int    s_ired[NW];
    __shared__ int    s_tcut;
    __shared__ int    lastFlag;

    // ---- Phase 1: elementwise + per-segment partials (first nelem blocks) ----
    if (flat < nelem) {
        int i = flat * NTH + tid;
        int half = tid & 15;
        float fv = 0.f, cv = 0.f;
        if (i < T) { fv = __expf(acts[i]); cv = LOG_GAMMA_F + __logf(1.f - fv); }
        if (i < PADT) { g_f[i] = fv; g_c[i] = cv; }
        float inc = cv;                               // inclusive scan of c, width 16
#pragma unroll
        for (int o = 1; o < 16; o <<= 1) { float n = __shfl_up_sync(FULLM, inc, o, 16); if (half >= o) inc += n; }
        float rt = (i < T) ? fv * __expf(inc - cv) : 0.f;   // f_j e^{localW_j}
        float vt = (i < T) ? __expf(inc * 0.001f) : 0.f;    // e^{localW_{j+1}/1000}
        float rs = rt, vs = vt;
#pragma unroll
        for (int o = 8; o > 0; o >>= 1) {
            rs += __shfl_xor_sync(FULLM, rs, o, 16);
            vs += __shfl_xor_sync(FULLM, vs, o, 16);
        }
        float cs = __shfl_sync(FULLM, inc, 15, 16);
        if (half == 0 && i < PADT) g_segpart[i >> 4] = make_float4(cs, rs, vs, 0.f);
        __syncthreads();
        if (tid == 0) { __threadfence(); atomicAdd(&g_elemdone, 1); }
    }

    if (producer) {
        // ---- Producer: minimal pre-publish path (volatile ready poll) ----
        if (tid == 0) {
            volatile int* vr = &g_elemdone;
            while (*vr < nelem) __nanosleep(64);
        }
        __syncthreads();
        __threadfence();
        float4 sp = g_segpart[tid];
        float ctot;
        float Wbase = block_scan_excl_f32(sp.x, ctot, s_warpf) + INIT_LOGW_F;
        float dfs = ALPHA_F * sp.y * __expf(Wbase);
        float dtot;
        float Pbase = block_scan_excl_f32(dfs, dtot, s_warpf) + INIT_LOGP_F;
        float qbase = __expf(Pbase);
        // publish DATA immediately — consumers wake on their own wq word.
        // qbase==0 (underflow) -> denormal marker so the word is never 0.
        float qstore = (qbase == 0.f) ? __uint_as_float(1u) : qbase;
        g_wq[tid] = make_float2(Wbase, qstore);
        // tcut = 16 * (1 + highest segment with qbase >= 1.4e-11)
        unsigned bal = __ballot_sync(FULLM, qbase >= 1.4e-11f);
        int lane = tid & 31, w = tid >> 5;
        int wmax = bal ? (w * 32 + (31 - __clz(bal)) + 1) : 0;
        if (lane == 0) s_ired[w] = wmax;
        __syncthreads();
        if (tid < 32) {
            int vv = (tid < NW) ? s_ired[tid] : 0;
#pragma unroll
            for (int o = 16; o > 0; o >>= 1) vv = max(vv, __shfl_down_sync(FULLM, vv, o));
            if (tid == 0) {
                s_tcut = vv * TCHUNK;
                __threadfence();
                atomicExch(&g_flag, vv * TCHUNK + 1);   // for tail loops only
            }
        }
        __syncthreads();
        // ---- Post-publish (overlaps consumers): S scan + prefix writes ----
        float wvs = sp.z * __expf(Wbase * 0.001f);
        double tot;
        double Sbase = block_scan_excl_f64((double)wvs, tot, s_warpd);
        {
            const float4* c4 = (const float4*)g_c;
            float v = __expf(Wbase * 0.001f);
            float ls = 0.f;
#pragma unroll
            for (int k = 0; k < 4; k++) {
                float4 c = c4[tid * 4 + k];
#pragma unroll
                for (int u = 0; u < 4; u++) {
                    float ce = (u == 0) ? c.x : (u == 1) ? c.y : (u == 2) ? c.z : c.w;
                    int i = tid * 16 + k * 4 + u;
                    v *= exp_tiny(ce * 0.001f);
                    if (i < T) { g_prefix[i] = Sbase + (double)ls; ls += v; }
                }
            }
        }
        if (tid == 0) g_prefix[T] = tot;
        // generic tail (includes the producer's own remapped chunk)
        int tcut = s_tcut;
        for (int chunk = cchunk; chunk * TCHUNK < tcut; chunk += GRIDY) {
            __syncthreads();
            compute_T2_smem(chunk, s_T2f);
            __syncthreads();
            if (lanes_ok) cold_resolve(chunk * TCHUNK, b4, u1, u2, T, B, s_T2f);
        }
    } else {
        // ---- Consumer pre-publish (overlapped): screen + candidate rc ----
        int cnt[4] = {0, 0, 0, 0};
        int ct[4][KCAND];
        float cu[4][KCAND];
        if (lanes_ok) {
            float4 v[TCHUNK];
#pragma unroll
            for (int t = 0; t < TCHUNK; t++)
                v[t] = (tstart + t < T) ? u2v[((size_t)(tstart + t) * B + b4) >> 2]
                                        : make_float4(0.f, 0.f, 0.f, 0.f);
#pragma unroll
            for (int t = 0; t < TCHUNK; t++) {
#pragma unroll
                for (int l = 0; l < 4; l++) {
                    float uv = (l == 0) ? v[t].x : (l == 1) ? v[t].y : (l == 2) ? v[t].z : v[t].w;
                    if (uv > U2MIN_GLOB) {
                        int n = cnt[l];
                        if (n == 0)      { ct[l][0] = t; cu[l][0] = uv; }
                        else if (n == 1) { ct[l][1] = t; cu[l][1] = uv; }
                        else if (n == 2) { ct[l][2] = t; cu[l][2] = uv; }
                        cnt[l] = n + 1;
                    }
                }
            }
        }
        float crc[4][KCAND];
#pragma unroll
        for (int l = 0; l < 4; l++) {
#pragma unroll
            for (int k = 0; k < KCAND; k++) {
                if (cnt[l] > k) {
                    size_t idx = (size_t)(tstart + ct[l][k]) * B + b4 + l;
                    float la = __logf(cu[l][k] + EPSF);
                    float lb = __logf(u1[idx] + EPSF);
                    crc[l][k] = (lb < 0.0f) ? __fdividef(la, lb) : 1e30f;
                }
            }
        }
        // ---- Pre-publish: warp 0 derives scan intermediates from acts ----
        if (tid < 32) {
            int half = tid & 15;
            int i = tstart + half;
            float fe = 0.f, ce = 0.f;
            if (i < T) { fe = __expf(acts[i]); ce = LOG_GAMMA_F + __logf(1.f - fe); }
            float inc = ce;
#pragma unroll
            for (int o = 1; o < 16; o <<= 1) { float n = __shfl_up_sync(FULLM, inc, o, 16); if (half >= o) inc += n; }
            float rt = (i < T) ? fe * __expf(inc - ce) : 0.f;
            float rinc = rt;
#pragma unroll
            for (int o = 1; o < 16; o <<= 1) { float n = __shfl_up_sync(FULLM, rinc, o, 16); if (half >= o) rinc += n; }
            float rexc = rinc - rt;
            // ---- Wake on our OWN wq word (self-publishing data, no fence) ----
            unsigned long long uv;
            volatile unsigned long long* p = (volatile unsigned long long*)&g_wq[cchunk];
            while ((uv = *p) == 0ull) __nanosleep(32);
            float Wb = __uint_as_float((unsigned)(uv & 0xffffffffu));
            float qb = __uint_as_float((unsigned)(uv >> 32));
            float q = qb * __expf(ALPHA_F * __expf(Wb) * rexc);
            if (tid < 16) s_T2f[half] = q * (1.0f + q + q * q) - 1e-12f;
        }
        __syncthreads();
        // ---- Compares (dead chunks self-reject: T2 <= -1e-12 or NaN) ----
        if (lanes_ok) {
#pragma unroll
            for (int l = 0; l < 4; l++) {
                int death_t = -1;
#pragma unroll
                for (int k = 0; k < KCAND; k++) {
                    if (death_t < 0 && cnt[l] > k && crc[l][k] < s_T2f[ct[l][k]])
                        death_t = ct[l][k];
                }
                if (death_t < 0 && cnt[l] > KCAND) {
                    for (int t = ct[l][KCAND - 1] + 1; t < TCHUNK; t++) {
                        size_t idx = (size_t)(tstart + t) * B + b4 + l;
                        float uv2 = u2[idx];
                        if (uv2 > U2MIN_GLOB) {
                            float la = __logf(uv2 + EPSF);
                            float lb = __logf(u1[idx] + EPSF);
                            float rc = (lb < 0.0f) ? __fdividef(la, lb) : 1e30f;
                            if (rc < s_T2f[t]) { death_t = t; break; }
                        }
                    }
                }
                if (death_t >= 0)
                    atomicMax(&g_deathX[b4 + l], T - (tstart + death_t));
            }
        }
        // ---- Tail chunks (never runs for this shape); flag is long set ----
        if (tid == 0) {
            volatile int* vf = &g_flag;
            int fv;
            while ((fv = *vf) == 0) __nanosleep(32);
            s_tcut = fv - 1;
        }
        __syncthreads();
        int tcut = s_tcut;
        for (int chunk = cchunk + GRIDY; chunk * TCHUNK < tcut; chunk += GRIDY) {
            __threadfence();
            __syncthreads();
            compute_T2_smem(chunk, s_T2f);
            __syncthreads();
            if (lanes_ok) cold_resolve(chunk * TCHUNK, b4, u1, u2, T, B, s_T2f);
        }
    }

    // ---- Completion: two-level arrival; final arriver reduces + resets ----
    if (tid == 0) {
        __threadfence();
        int bucket = flat & 7;
        int quota = (nblocks - bucket + 7) >> 3;
        int lf = 0;
        if (atomicAdd(&g_done8[bucket], 1) == quota - 1)
            lf = (atomicAdd(&g_done, 1) == 7);
        lastFlag = lf;
    }
    __syncthreads();
    if (!lastFlag) return;

    __shared__ double s_red[NW];
    double prefTot = g_prefix[T];
    double s = 0.0;
    for (int i = tid; i < B; i += NTH) {
        int dx = g_deathX[i];
        s += (dx == 0) ? prefTot : g_prefix[T - dx];   // fast path: alive lanes
    }
#pragma unroll
    for (int o = 16; o > 0; o >>= 1) s += __shfl_down_sync(FULLM, s, o);
    if ((tid & 31) == 0) s_red[tid >> 5] = s;
    __syncthreads();
    if (tid < 32) {
        double v = (tid < NW) ? s_red[tid] : 0.0;
#pragma unroll
        for (int o = 16; o > 0; o >>= 1) v += __shfl_down_sync(FULLM, v, o);
        if (tid == 0) out[0] = (float)(v / (double)B);
    }
    __syncthreads();
    for (int i = tid; i < B; i += NTH) g_deathX[i] = 0;            // reset deaths
    for (int i = tid; i < NSEG; i += NTH)
        *(unsigned long long*)&g_wq[i] = 0ull;                     // reset wq words
    if (tid < 8) g_done8[tid] = 0;
    if (tid == 0) { g_flag = 0; g_elemdone = 0; g_done = 0; }
}

extern "C" void kernel_launch(void* const* d_in, const int* in_sizes, int n_in,
                              void* d_out, int out_size) {
    const float* acts = (const float*)d_in[0];
    const float* u1   = (const float*)d_in[1];
    const float* u2   = (const float*)d_in[2];
    int T = in_sizes[0];
    int B = (T > 0) ? (in_sizes[1] / T) : 0;

    int gx = (B + NTH * 4 - 1) / (NTH * 4);           // 2 for B=4096
    dim3 grid(gx, GRIDY);                             // 148 blocks total
    int nblocks = gx * GRIDY;
    int nelem = PADT / NTH;                           // 16
    k_all<<<grid, NTH>>>(acts, u1, u2, (float*)d_out, T, B, nelem, nblocks);
}